// round 9
// baseline (speedup 1.0000x reference)
#include <cuda_runtime.h>

typedef unsigned long long U64;

#define NUM_HEADS 8
#define HDIM 512
#define NGRAPH 256
#define TILE 16
#define CH 128      // nodes per CTA in main_kernel
#define XROW 520    // x tile row stride (floats); K-halves at offsets 0 and 260
#define HGAP 260
#define QROW 524    // qk row stride (floats); K-halves at 0 and 260

// ---------------- device scratch (no allocations allowed) ----------------
__device__ float g_qk[NUM_HEADS * HDIM];
__device__ float g_y[NGRAPH][NUM_HEADS][HDIM];
__device__ float g_denom[NGRAPH][NUM_HEADS];
__device__ float g_att[NGRAPH][HDIM];

// ---------------- helpers ----------------
__device__ __forceinline__ U64 fma2(U64 a, U64 b, U64 c) {
    U64 d;
    asm("fma.rn.f32x2 %0, %1, %2, %3;" : "=l"(d) : "l"(a), "l"(b), "l"(c));
    return d;
}
__device__ __forceinline__ U64 dup2(float x) {
    U64 d; unsigned xi = __float_as_uint(x);
    asm("mov.b64 %0, {%1, %1};" : "=l"(d) : "r"(xi));
    return d;
}
__device__ __forceinline__ float lo2(U64 v) { return __uint_as_float((unsigned)(v & 0xffffffffu)); }
__device__ __forceinline__ float hi2(U64 v) { return __uint_as_float((unsigned)(v >> 32)); }

__device__ __forceinline__ void cpa16(void* dst, const void* src) {
    unsigned d = (unsigned)__cvta_generic_to_shared(dst);
    asm volatile("cp.async.cg.shared.global [%0], [%1], 16;\n" :: "r"(d), "l"(src));
}
#define CP_COMMIT() asm volatile("cp.async.commit_group;\n" ::: "memory")
#define CP_WAIT0()  asm volatile("cp.async.wait_group 0;\n" ::: "memory")

// ---------------- zero kernels (atomic accumulators need clean state) ----------------
__global__ void zero_y_kernel() {
    int i = (blockIdx.x * 256 + threadIdx.x) * 4;   // 1024 CTAs -> exactly 1,048,576 floats
    *(float4*)&(((float*)g_y)[i]) = make_float4(0.f, 0.f, 0.f, 0.f);
}
__global__ void zero_d_kernel() {
    int i = blockIdx.x * 256 + threadIdx.x;          // 8 CTAs -> 2048 floats
    ((float*)g_denom)[i] = 0.f;
}

// ---------------- kernel: qk fold (64 CTAs, smem-staged coalesced) ----------------
__global__ __launch_bounds__(256) void qk_kernel(const float* __restrict__ q,
                                                 const float* __restrict__ kw) {
    __shared__ float tile[64 * 65];
    __shared__ float qs[64];
    __shared__ float part[4][64];
    const int h = blockIdx.x >> 3, jb = blockIdx.x & 7;
    const int t = threadIdx.x;
    if (t < 64) qs[t] = q[h * 64 + t];
    for (int k = t; k < 1024; k += 256) {
        int r = k >> 4, cc = k & 15;
        float4 v = *(const float4*)&kw[(size_t)(h * 64 + r) * HDIM + jb * 64 + cc * 4];
        float* dst = &tile[r * 65 + cc * 4];
        dst[0] = v.x; dst[1] = v.y; dst[2] = v.z; dst[3] = v.w;
    }
    __syncthreads();
    const int c = t & 63, ds = t >> 6;
    float s = 0.f;
#pragma unroll
    for (int d = 0; d < 16; d++) s += qs[ds * 16 + d] * tile[(ds * 16 + d) * 65 + c];
    part[ds][c] = s;
    __syncthreads();
    if (t < 64)
        g_qk[h * HDIM + jb * 64 + t] =
            (part[0][t] + part[1][t] + part[2][t] + part[3][t]) * 0.125f;
}

// ---------------- main: node-parallel, atomic flush at graph boundaries ----------------
// CTA owns CH=128 contiguous nodes (8 x 16-node tiles). Per tile:
//   Phase A: w[n,h] = exp(x[n]·qk[h])  (kh = t&1 K-half, hh = (t>>1)&7 head, ng = t>>4 row)
//   Phase B: acc[h, c0..c0+1] += w[n,h]*x[n,c]; graph boundary -> atomicAdd flush.
__global__ __launch_bounds__(256, 4)
void main_kernel(const float* __restrict__ x, const int* __restrict__ batch, int N) {
    extern __shared__ float sm[];
    float* xs = sm;                        // [TILE][XROW] = 8320 floats
    float* qs = sm + TILE * XROW;          // [8][QROW]    = 4192 floats
    float* ws = qs + 8 * QROW;             // [TILE*8]     = 128 floats
    int*   bs = (int*)(ws + TILE * 8);     // [TILE]

    const int t = threadIdx.x;
    const int n0 = blockIdx.x * CH;
    const int nend = min(n0 + CH, N);

    // stage qk with K-half gap layout
    for (int k = t; k < 8 * HDIM; k += 256) {
        int h = k >> 9, j = k & 511;
        qs[h * QROW + j + (j >= 256 ? 4 : 0)] = g_qk[k];
    }

    const int kh = t & 1, hh = (t >> 1) & 7, ng = t >> 4;
    const int c0 = 2 * t;
    const int xoffb = c0 + (c0 >= 256 ? 4 : 0);

    U64 acc[2][4];
#pragma unroll
    for (int a = 0; a < 2; a++)
#pragma unroll
        for (int p = 0; p < 4; p++) acc[a][p] = 0ull;
    float dpart = 0.f;
    int cur_g = -1;

#define FLUSH() do {                                                          \
        _Pragma("unroll")                                                     \
        for (int p = 0; p < 4; p++) {                                         \
            atomicAdd(&g_y[cur_g][2 * p][c0],         lo2(acc[0][p]));        \
            atomicAdd(&g_y[cur_g][2 * p][c0 + 1],     lo2(acc[1][p]));        \
            atomicAdd(&g_y[cur_g][2 * p + 1][c0],     hi2(acc[0][p]));        \
            atomicAdd(&g_y[cur_g][2 * p + 1][c0 + 1], hi2(acc[1][p]));        \
            acc[0][p] = 0ull; acc[1][p] = 0ull;                               \
        }                                                                     \
        if (t < 8) { atomicAdd(&g_denom[cur_g][t], dpart); dpart = 0.f; }     \
    } while (0)

    for (int base = n0; base < nend; base += TILE) {
        const int tc = min(TILE, nend - base);

        if (t < tc) bs[t] = batch[base + t];
#pragma unroll
        for (int k = 0; k < 8; k++) {
            int idx = t + k * 256;
            int r = idx >> 7, cc = idx & 127;
            int col4 = cc * 4;
            if (r < tc)
                cpa16(xs + r * XROW + col4 + (col4 >= 256 ? 4 : 0),
                      &x[(size_t)(base + r) * HDIM + col4]);
        }
        CP_COMMIT();
        CP_WAIT0();
        __syncthreads();   // tile + bs (+ qs on first iter) visible

        // ---- Phase A ----
        {
            const float* xr = xs + ng * XROW + kh * HGAP;
            const float* qr = qs + hh * QROW + kh * HGAP;
            U64 a0 = 0, a1 = 0, a2 = 0, a3 = 0;
#pragma unroll 4
            for (int j = 0; j < 256; j += 8) {
                ulonglong2 xv0 = *(const ulonglong2*)&xr[j];
                ulonglong2 qv0 = *(const ulonglong2*)&qr[j];
                ulonglong2 xv1 = *(const ulonglong2*)&xr[j + 4];
                ulonglong2 qv1 = *(const ulonglong2*)&qr[j + 4];
                a0 = fma2(xv0.x, qv0.x, a0);
                a1 = fma2(xv0.y, qv0.y, a1);
                a2 = fma2(xv1.x, qv1.x, a2);
                a3 = fma2(xv1.y, qv1.y, a3);
            }
            float sh = lo2(a0) + hi2(a0) + lo2(a1) + hi2(a1)
                     + lo2(a2) + hi2(a2) + lo2(a3) + hi2(a3);
            sh += __shfl_xor_sync(~0u, sh, 1);
            if (kh == 0) ws[ng * 8 + hh] = (ng < tc) ? __expf(sh) : 0.f;
        }
        __syncthreads();

        // ---- Phase B with graph-boundary flush (branch is CTA-uniform) ----
        for (int i = 0; i < tc; i++) {
            int gi = bs[i];
            if (gi != cur_g) {
                if (cur_g >= 0) FLUSH();
                cur_g = gi;
            }
            float2 xv = *(const float2*)&xs[i * XROW + xoffb];
            ulonglong2 w01 = *(const ulonglong2*)&ws[i * 8];
            ulonglong2 w23 = *(const ulonglong2*)&ws[i * 8 + 4];
            if (t < 8) dpart += ws[i * 8 + t];
            U64 xa = dup2(xv.x), xb2 = dup2(xv.y);
            acc[0][0] = fma2(w01.x, xa, acc[0][0]);
            acc[0][1] = fma2(w01.y, xa, acc[0][1]);
            acc[0][2] = fma2(w23.x, xa, acc[0][2]);
            acc[0][3] = fma2(w23.y, xa, acc[0][3]);
            acc[1][0] = fma2(w01.x, xb2, acc[1][0]);
            acc[1][1] = fma2(w01.y, xb2, acc[1][1]);
            acc[1][2] = fma2(w23.x, xb2, acc[1][2]);
            acc[1][3] = fma2(w23.y, xb2, acc[1][3]);
        }
        __syncthreads();   // xs/ws fully consumed before next tile overwrite
    }

    if (cur_g >= 0) FLUSH();
#undef FLUSH
}

// ---------------- v-projection: grid (64 graph-blocks of 4, 8 heads) ----------------
__global__ __launch_bounds__(256) void vproj_kernel(const float* __restrict__ vw,
                                                    const float* __restrict__ vb) {
    __shared__ float Yn[4][HDIM];          // 8KB normalized Y
    __shared__ float wt[2][64][68];        // 34.8KB double-buffered weights
    __shared__ float invs[4], nzf[4];
    const int gb = blockIdx.x, h = blockIdx.y, t = threadIdx.x;

    if (t < 4) {
        float d = g_denom[gb * 4 + t][h];
        invs[t] = d > 0.f ? 1.f / d : 0.f;
        nzf[t]  = d > 0.f ? 1.f : 0.f;
    }
    __syncthreads();

    for (int k = t * 4; k < 4 * HDIM; k += 1024) {
        int r = k >> 9, cidx = k & 511;
        float4 v = *(const float4*)&g_y[gb * 4 + r][h][cidx];
        float s = invs[r];
        v.x *= s; v.y *= s; v.z *= s; v.w *= s;
        *(float4*)&Yn[r][cidx] = v;
    }

#define LOAD_W(KC, BUF) do {                                                  \
        _Pragma("unroll")                                                     \
        for (int k = 0; k < 4; k++) {                                         \
            int idx = t + k * 256;                                            \
            int r = idx >> 4, cc = idx & 15;                                  \
            cpa16(&wt[BUF][r][cc * 4],                                        \
                  &vw[(size_t)(h * 64 + r) * HDIM + (KC) + cc * 4]);          \
        }                                                                     \
    } while (0)

    LOAD_W(0, 0);
    CP_COMMIT();

    const int c = t & 63, gq = t >> 6;     // one output: (graph gq, col c)
    U64 a0 = 0ull, a1 = 0ull;

    for (int ch = 0; ch < 8; ch++) {
        CP_WAIT0();
        __syncthreads();
        if (ch + 1 < 8) LOAD_W((ch + 1) * 64, (ch + 1) & 1);
        CP_COMMIT();

        const float* wr = &wt[ch & 1][c][0];
#pragma unroll
        for (int j = 0; j < 64; j += 4) {
            ulonglong2 w2 = *(const ulonglong2*)&wr[j];
            ulonglong2 ya = *(const ulonglong2*)&Yn[gq][ch * 64 + j];
            a0 = fma2(w2.x, ya.x, a0);
            a1 = fma2(w2.y, ya.y, a1);
        }
        __syncthreads();
    }
#undef LOAD_W

    float b = vb[h * 64 + c];
    float r = lo2(a0) + hi2(a0) + lo2(a1) + hi2(a1);
    g_att[gb * 4 + gq][h * 64 + c] = r + nzf[gq] * b;
}

// ---------------- output projection: grid (64 graph-blocks of 4, 8 col-blocks) ----------------
__global__ __launch_bounds__(256) void oproj_kernel(const float* __restrict__ ow,
                                                    const float* __restrict__ ob,
                                                    float* __restrict__ out) {
    __shared__ float As[4][HDIM];
    __shared__ float wt[2][64][68];
    const int gb = blockIdx.x, ib = blockIdx.y, t = threadIdx.x;

    for (int k = t * 4; k < 4 * HDIM; k += 1024) {
        int r = k >> 9, cidx = k & 511;
        *(float4*)&As[r][cidx] = *(const float4*)&g_att[gb * 4 + r][cidx];
    }

#define LOAD_W(KC, BUF) do {                                                  \
        _Pragma("unroll")                                                     \
        for (int k = 0; k < 4; k++) {                                         \
            int idx = t + k * 256;                                            \
            int r = idx >> 4, cc = idx & 15;                                  \
            cpa16(&wt[BUF][r][cc * 4],                                        \
                  &ow[(size_t)(ib * 64 + r) * HDIM + (KC) + cc * 4]);         \
        }                                                                     \
    } while (0)

    LOAD_W(0, 0);
    CP_COMMIT();

    const int c = t & 63, gq = t >> 6;
    U64 a0 = 0ull, a1 = 0ull;

    for (int ch = 0; ch < 8; ch++) {
        CP_WAIT0();
        __syncthreads();
        if (ch + 1 < 8) LOAD_W((ch + 1) * 64, (ch + 1) & 1);
        CP_COMMIT();

        const float* wr = &wt[ch & 1][c][0];
#pragma unroll
        for (int j = 0; j < 64; j += 4) {
            ulonglong2 w2 = *(const ulonglong2*)&wr[j];
            ulonglong2 ya = *(const ulonglong2*)&As[gq][ch * 64 + j];
            a0 = fma2(w2.x, ya.x, a0);
            a1 = fma2(w2.y, ya.y, a1);
        }
        __syncthreads();
    }
#undef LOAD_W

    float b = ob[ib * 64 + c];
    float r = lo2(a0) + hi2(a0) + lo2(a1) + hi2(a1);
    out[(size_t)(gb * 4 + gq) * HDIM + ib * 64 + c] = r + b;
}

// ---------------- layer norm (in place on d_out) ----------------
__global__ void ln_kernel(const float* __restrict__ gam, const float* __restrict__ bet,
                          float* __restrict__ out) {
    __shared__ float red1[8], red2[8], stats[2];
    int r = blockIdx.x, t = threadIdx.x;
    float v0 = out[(size_t)r * HDIM + t];
    float v1 = out[(size_t)r * HDIM + t + 256];
    float s1 = v0 + v1, s2 = v0 * v0 + v1 * v1;
#pragma unroll
    for (int o = 16; o; o >>= 1) {
        s1 += __shfl_xor_sync(~0u, s1, o);
        s2 += __shfl_xor_sync(~0u, s2, o);
    }
    if ((t & 31) == 0) { red1[t >> 5] = s1; red2[t >> 5] = s2; }
    __syncthreads();
    if (t == 0) {
        float a = 0.f, b = 0.f;
        for (int k = 0; k < 8; k++) { a += red1[k]; b += red2[k]; }
        float mu = a * (1.f / 512.f);
        stats[0] = mu;
        stats[1] = rsqrtf(b * (1.f / 512.f) - mu * mu + 1e-5f);
    }
    __syncthreads();
    float mu = stats[0], rs = stats[1];
    out[(size_t)r * HDIM + t]       = (v0 - mu) * rs * gam[t] + bet[t];
    out[(size_t)r * HDIM + t + 256] = (v1 - mu) * rs * gam[t + 256] + bet[t + 256];
}

// ---------------- launch ----------------
extern "C" void kernel_launch(void* const* d_in, const int* in_sizes, int n_in,
                              void* d_out, int out_size) {
    const float* x     = (const float*)d_in[0];
    const int*   batch = (const int*)d_in[1];
    const float* q     = (const float*)d_in[2];
    const float* kw    = (const float*)d_in[3];
    // d_in[4] = k_b: cancels in segment softmax (per-head constant shift) — unused
    const float* vw    = (const float*)d_in[5];
    const float* vb    = (const float*)d_in[6];
    const float* ow    = (const float*)d_in[7];
    const float* ob    = (const float*)d_in[8];
    const float* lng   = (const float*)d_in[9];
    const float* lnb   = (const float*)d_in[10];
    float* out = (float*)d_out;

    int N = in_sizes[0] / HDIM;

    zero_y_kernel<<<1024, 256>>>();                 // launch 1
    zero_d_kernel<<<8, 256>>>();                    // launch 2
    qk_kernel<<<64, 256>>>(q, kw);                  // launch 3

    int NT = (N + CH - 1) / CH;
    size_t smem = (TILE * XROW + 8 * QROW + TILE * 8) * sizeof(float) + TILE * sizeof(int);
    cudaFuncSetAttribute(main_kernel, cudaFuncAttributeMaxDynamicSharedMemorySize, (int)smem);
    main_kernel<<<NT, 256, smem>>>(x, batch, N);    // launch 4 (profiled slot)

    vproj_kernel<<<dim3(64, NUM_HEADS), 256>>>(vw, vb);
    oproj_kernel<<<dim3(64, NUM_HEADS), 256>>>(ow, ob, out);
    ln_kernel<<<NGRAPH, 256>>>(lng, lnb, out);
}

// round 10
// speedup vs baseline: 1.9734x; 1.9734x over previous
#include <cuda_runtime.h>

typedef unsigned long long U64;

#define NUM_HEADS 8
#define HDIM 512
#define NGRAPH 256
#define CH 128      // nodes per CTA (2 node-lanes x 64 nodes)

// ---------------- device scratch (no allocations allowed) ----------------
__device__ float g_qk[NUM_HEADS * HDIM];
__device__ float g_y[NGRAPH][NUM_HEADS][HDIM];
__device__ float g_denom[NGRAPH][NUM_HEADS];
__device__ float g_att[NGRAPH][HDIM];

// ---------------- f32x2 helpers ----------------
__device__ __forceinline__ U64 fma2(U64 a, U64 b, U64 c) {
    U64 d;
    asm("fma.rn.f32x2 %0, %1, %2, %3;" : "=l"(d) : "l"(a), "l"(b), "l"(c));
    return d;
}
__device__ __forceinline__ U64 add2(U64 a, U64 b) {
    U64 d;
    asm("add.rn.f32x2 %0, %1, %2;" : "=l"(d) : "l"(a), "l"(b));
    return d;
}
__device__ __forceinline__ U64 dup2(float x) {
    U64 d; unsigned xi = __float_as_uint(x);
    asm("mov.b64 %0, {%1, %1};" : "=l"(d) : "r"(xi));
    return d;
}
__device__ __forceinline__ float lo2(U64 v) { return __uint_as_float((unsigned)(v & 0xffffffffu)); }
__device__ __forceinline__ float hi2(U64 v) { return __uint_as_float((unsigned)(v >> 32)); }

__device__ __forceinline__ void cpa16(void* dst, const void* src) {
    unsigned d = (unsigned)__cvta_generic_to_shared(dst);
    asm volatile("cp.async.cg.shared.global [%0], [%1], 16;\n" :: "r"(d), "l"(src));
}
#define CP_COMMIT() asm volatile("cp.async.commit_group;\n" ::: "memory")
#define CP_WAIT0()  asm volatile("cp.async.wait_group 0;\n" ::: "memory")

// ---------------- zero kernels (atomic accumulators) ----------------
__global__ void zero_y_kernel() {
    int i = (blockIdx.x * 256 + threadIdx.x) * 4;   // 1024 CTAs -> 1,048,576 floats
    *(float4*)&(((float*)g_y)[i]) = make_float4(0.f, 0.f, 0.f, 0.f);
}
__global__ void zero_d_kernel() {
    int i = blockIdx.x * 256 + threadIdx.x;          // 8 CTAs -> 2048 floats
    ((float*)g_denom)[i] = 0.f;
}

// ---------------- qk fold (64 CTAs, smem-staged coalesced) ----------------
__global__ __launch_bounds__(256) void qk_kernel(const float* __restrict__ q,
                                                 const float* __restrict__ kw) {
    __shared__ float tile[64 * 65];
    __shared__ float qs[64];
    __shared__ float part[4][64];
    const int h = blockIdx.x >> 3, jb = blockIdx.x & 7;
    const int t = threadIdx.x;
    if (t < 64) qs[t] = q[h * 64 + t];
    for (int k = t; k < 1024; k += 256) {
        int r = k >> 4, cc = k & 15;
        float4 v = *(const float4*)&kw[(size_t)(h * 64 + r) * HDIM + jb * 64 + cc * 4];
        float* dst = &tile[r * 65 + cc * 4];
        dst[0] = v.x; dst[1] = v.y; dst[2] = v.z; dst[3] = v.w;
    }
    __syncthreads();
    const int c = t & 63, ds = t >> 6;
    float s = 0.f;
#pragma unroll
    for (int d = 0; d < 16; d++) s += qs[ds * 16 + d] * tile[(ds * 16 + d) * 65 + c];
    part[ds][c] = s;
    __syncthreads();
    if (t < 64)
        g_qk[h * HDIM + jb * 64 + t] =
            (part[0][t] + part[1][t] + part[2][t] + part[3][t]) * 0.125f;
}

// ---------------- main: warp-autonomous, fully register-resident ----------------
// Warp w of CTA: head-group hg = w&3 (heads 2hg, 2hg+1), node-lane nl = w>>2.
// Lane owns 16 dims as 8 f32x2 pairs: dim pair p at float index (p*32+lane)*2.
// Per node: 8 LDG.64 (coalesced 256B/pair) -> Phase A vs stationary q regs ->
// intra-warp shfl butterfly for s -> w = exp(s) -> Phase B into Y regs.
// Graph boundary -> atomicAdd flush (spread REDG). No smem, no __syncthreads.
__global__ __launch_bounds__(256, 2)
void main_kernel(const float* __restrict__ x, const int* __restrict__ batch, int N) {
    const int t = threadIdx.x;
    const int lane = t & 31;
    const int w = t >> 5;
    const int h0 = (w & 3) * 2;      // first head of this warp's pair
    const int nl = w >> 2;           // node-lane 0/1

    // stationary folded-query regs (2 heads x 8 pairs)
    U64 q0[8], q1[8];
#pragma unroll
    for (int p = 0; p < 8; p++) {
        int d = (p * 32 + lane) * 2;
        q0[p] = *(const U64*)&g_qk[h0 * HDIM + d];
        q1[p] = *(const U64*)&g_qk[(h0 + 1) * HDIM + d];
    }

    U64 Y0[8], Y1[8];
#pragma unroll
    for (int p = 0; p < 8; p++) { Y0[p] = 0ull; Y1[p] = 0ull; }
    U64 dp = 0ull;                   // packed denom partials {sum w0, sum w1}
    int cur_g = -1;

    const int nbeg = blockIdx.x * CH + nl * (CH / 2);
    const int nlim = min(nbeg + CH / 2, N);

#define FLUSH() do {                                                          \
        _Pragma("unroll")                                                     \
        for (int p = 0; p < 8; p++) {                                         \
            int d = (p * 32 + lane) * 2;                                      \
            atomicAdd(&g_y[cur_g][h0][d],         lo2(Y0[p]));                \
            atomicAdd(&g_y[cur_g][h0][d + 1],     hi2(Y0[p]));                \
            atomicAdd(&g_y[cur_g][h0 + 1][d],     lo2(Y1[p]));                \
            atomicAdd(&g_y[cur_g][h0 + 1][d + 1], hi2(Y1[p]));                \
            Y0[p] = 0ull; Y1[p] = 0ull;                                       \
        }                                                                     \
        if (lane == 0) {                                                      \
            atomicAdd(&g_denom[cur_g][h0],     lo2(dp));                      \
            atomicAdd(&g_denom[cur_g][h0 + 1], hi2(dp));                      \
        }                                                                     \
        dp = 0ull;                                                            \
    } while (0)

    for (int n = nbeg; n < nlim; n++) {
        int g = batch[n];                     // warp-uniform broadcast, L1-hit
        if (g != cur_g) {
            if (cur_g >= 0) FLUSH();
            cur_g = g;
        }

        const float* xr = x + (size_t)n * HDIM;
        U64 xv[8];
#pragma unroll
        for (int p = 0; p < 8; p++)
            xv[p] = *(const U64*)&xr[(p * 32 + lane) * 2];

        // Phase A: partial dots vs stationary q
        U64 a0 = 0ull, a1 = 0ull;
#pragma unroll
        for (int p = 0; p < 8; p++) {
            a0 = fma2(xv[p], q0[p], a0);
            a1 = fma2(xv[p], q1[p], a1);
        }
        float s0 = lo2(a0) + hi2(a0);
        float s1 = lo2(a1) + hi2(a1);
#pragma unroll
        for (int o = 16; o; o >>= 1) {
            s0 += __shfl_xor_sync(~0u, s0, o);
            s1 += __shfl_xor_sync(~0u, s1, o);
        }
        float w0 = __expf(s0), w1 = __expf(s1);
        dp = add2(dp, dup2(0.f) | ((U64)__float_as_uint(w1) << 32) | __float_as_uint(w0));

        // Phase B: Y += w * x (register accumulators)
        U64 wd0 = dup2(w0), wd1 = dup2(w1);
#pragma unroll
        for (int p = 0; p < 8; p++) {
            Y0[p] = fma2(wd0, xv[p], Y0[p]);
            Y1[p] = fma2(wd1, xv[p], Y1[p]);
        }
    }

    if (cur_g >= 0) FLUSH();
#undef FLUSH
}

// ---------------- v-projection: grid (64 graph-blocks of 4, 8 heads) ----------------
__global__ __launch_bounds__(256) void vproj_kernel(const float* __restrict__ vw,
                                                    const float* __restrict__ vb) {
    __shared__ float Yn[4][HDIM];
    __shared__ float wt[2][64][68];
    __shared__ float invs[4], nzf[4];
    const int gb = blockIdx.x, h = blockIdx.y, t = threadIdx.x;

    if (t < 4) {
        float d = g_denom[gb * 4 + t][h];
        invs[t] = d > 0.f ? 1.f / d : 0.f;
        nzf[t]  = d > 0.f ? 1.f : 0.f;
    }
    __syncthreads();

    for (int k = t * 4; k < 4 * HDIM; k += 1024) {
        int r = k >> 9, cidx = k & 511;
        float4 v = *(const float4*)&g_y[gb * 4 + r][h][cidx];
        float s = invs[r];
        v.x *= s; v.y *= s; v.z *= s; v.w *= s;
        *(float4*)&Yn[r][cidx] = v;
    }

#define LOAD_W(KC, BUF) do {                                                  \
        _Pragma("unroll")                                                     \
        for (int k = 0; k < 4; k++) {                                         \
            int idx = t + k * 256;                                            \
            int r = idx >> 4, cc = idx & 15;                                  \
            cpa16(&wt[BUF][r][cc * 4],                                        \
                  &vw[(size_t)(h * 64 + r) * HDIM + (KC) + cc * 4]);          \
        }                                                                     \
    } while (0)

    LOAD_W(0, 0);
    CP_COMMIT();

    const int c = t & 63, gq = t >> 6;
    U64 a0 = 0ull, a1 = 0ull;

    for (int ch = 0; ch < 8; ch++) {
        CP_WAIT0();
        __syncthreads();
        if (ch + 1 < 8) LOAD_W((ch + 1) * 64, (ch + 1) & 1);
        CP_COMMIT();

        const float* wr = &wt[ch & 1][c][0];
#pragma unroll
        for (int j = 0; j < 64; j += 4) {
            ulonglong2 w2 = *(const ulonglong2*)&wr[j];
            ulonglong2 ya = *(const ulonglong2*)&Yn[gq][ch * 64 + j];
            a0 = fma2(w2.x, ya.x, a0);
            a1 = fma2(w2.y, ya.y, a1);
        }
        __syncthreads();
    }
#undef LOAD_W

    float b = vb[h * 64 + c];
    float r = lo2(a0) + hi2(a0) + lo2(a1) + hi2(a1);
    g_att[gb * 4 + gq][h * 64 + c] = r + nzf[gq] * b;
}

// ---------------- output projection: grid (64 graph-blocks of 4, 8 col-blocks) ----------------
__global__ __launch_bounds__(256) void oproj_kernel(const float* __restrict__ ow,
                                                    const float* __restrict__ ob,
                                                    float* __restrict__ out) {
    __shared__ float As[4][HDIM];
    __shared__ float wt[2][64][68];
    const int gb = blockIdx.x, ib = blockIdx.y, t = threadIdx.x;

    for (int k = t * 4; k < 4 * HDIM; k += 1024) {
        int r = k >> 9, cidx = k & 511;
        *(float4*)&As[r][cidx] = *(const float4*)&g_att[gb * 4 + r][cidx];
    }

#define LOAD_W(KC, BUF) do {                                                  \
        _Pragma("unroll")                                                     \
        for (int k = 0; k < 4; k++) {                                         \
            int idx = t + k * 256;                                            \
            int r = idx >> 4, cc = idx & 15;                                  \
            cpa16(&wt[BUF][r][cc * 4],                                        \
                  &ow[(size_t)(ib * 64 + r) * HDIM + (KC) + cc * 4]);         \
        }                                                                     \
    } while (0)

    LOAD_W(0, 0);
    CP_COMMIT();

    const int c = t & 63, gq = t >> 6;
    U64 a0 = 0ull, a1 = 0ull;

    for (int ch = 0; ch < 8; ch++) {
        CP_WAIT0();
        __syncthreads();
        if (ch + 1 < 8) LOAD_W((ch + 1) * 64, (ch + 1) & 1);
        CP_COMMIT();

        const float* wr = &wt[ch & 1][c][0];
#pragma unroll
        for (int j = 0; j < 64; j += 4) {
            ulonglong2 w2 = *(const ulonglong2*)&wr[j];
            ulonglong2 ya = *(const ulonglong2*)&As[gq][ch * 64 + j];
            a0 = fma2(w2.x, ya.x, a0);
            a1 = fma2(w2.y, ya.y, a1);
        }
        __syncthreads();
    }
#undef LOAD_W

    float b = ob[ib * 64 + c];
    float r = lo2(a0) + hi2(a0) + lo2(a1) + hi2(a1);
    out[(size_t)(gb * 4 + gq) * HDIM + ib * 64 + c] = r + b;
}

// ---------------- layer norm (in place on d_out) ----------------
__global__ void ln_kernel(const float* __restrict__ gam, const float* __restrict__ bet,
                          float* __restrict__ out) {
    __shared__ float red1[8], red2[8], stats[2];
    int r = blockIdx.x, t = threadIdx.x;
    float v0 = out[(size_t)r * HDIM + t];
    float v1 = out[(size_t)r * HDIM + t + 256];
    float s1 = v0 + v1, s2 = v0 * v0 + v1 * v1;
#pragma unroll
    for (int o = 16; o; o >>= 1) {
        s1 += __shfl_xor_sync(~0u, s1, o);
        s2 += __shfl_xor_sync(~0u, s2, o);
    }
    if ((t & 31) == 0) { red1[t >> 5] = s1; red2[t >> 5] = s2; }
    __syncthreads();
    if (t == 0) {
        float a = 0.f, b = 0.f;
        for (int k = 0; k < 8; k++) { a += red1[k]; b += red2[k]; }
        float mu = a * (1.f / 512.f);
        stats[0] = mu;
        stats[1] = rsqrtf(b * (1.f / 512.f) - mu * mu + 1e-5f);
    }
    __syncthreads();
    float mu = stats[0], rs = stats[1];
    out[(size_t)r * HDIM + t]       = (v0 - mu) * rs * gam[t] + bet[t];
    out[(size_t)r * HDIM + t + 256] = (v1 - mu) * rs * gam[t + 256] + bet[t + 256];
}

// ---------------- launch ----------------
extern "C" void kernel_launch(void* const* d_in, const int* in_sizes, int n_in,
                              void* d_out, int out_size) {
    const float* x     = (const float*)d_in[0];
    const int*   batch = (const int*)d_in[1];
    const float* q     = (const float*)d_in[2];
    const float* kw    = (const float*)d_in[3];
    // d_in[4] = k_b: cancels in segment softmax (per-head constant shift) — unused
    const float* vw    = (const float*)d_in[5];
    const float* vb    = (const float*)d_in[6];
    const float* ow    = (const float*)d_in[7];
    const float* ob    = (const float*)d_in[8];
    const float* lng   = (const float*)d_in[9];
    const float* lnb   = (const float*)d_in[10];
    float* out = (float*)d_out;

    int N = in_sizes[0] / HDIM;

    zero_y_kernel<<<1024, 256>>>();                 // launch 1
    zero_d_kernel<<<8, 256>>>();                    // launch 2
    qk_kernel<<<64, 256>>>(q, kw);                  // launch 3

    int NT = (N + CH - 1) / CH;
    main_kernel<<<NT, 256>>>(x, batch, N);          // launch 4 (profiled slot)

    vproj_kernel<<<dim3(64, NUM_HEADS), 256>>>(vw, vb);
    oproj_kernel<<<dim3(64, NUM_HEADS), 256>>>(ow, ob, out);
    ln_kernel<<<NGRAPH, 256>>>(lng, lnb, out);
}

// round 11
// speedup vs baseline: 2.3150x; 1.1731x over previous
#include <cuda_runtime.h>

typedef unsigned long long U64;

#define NUM_HEADS 8
#define HDIM 512
#define NGRAPH 256
#define CH 128      // nodes per CTA (2 node-lanes x 64 nodes)

// ---------------- device scratch (no allocations allowed) ----------------
__device__ float g_qk[NUM_HEADS * HDIM];
__device__ float g_y[NGRAPH][NUM_HEADS][HDIM];
__device__ float g_denom[NGRAPH][NUM_HEADS];
__device__ float g_att[NGRAPH][HDIM];

// ---------------- f32x2 helpers ----------------
__device__ __forceinline__ U64 fma2(U64 a, U64 b, U64 c) {
    U64 d;
    asm("fma.rn.f32x2 %0, %1, %2, %3;" : "=l"(d) : "l"(a), "l"(b), "l"(c));
    return d;
}
__device__ __forceinline__ U64 add2(U64 a, U64 b) {
    U64 d;
    asm("add.rn.f32x2 %0, %1, %2;" : "=l"(d) : "l"(a), "l"(b));
    return d;
}
__device__ __forceinline__ U64 dup2(float x) {
    U64 d; unsigned xi = __float_as_uint(x);
    asm("mov.b64 %0, {%1, %1};" : "=l"(d) : "r"(xi));
    return d;
}
__device__ __forceinline__ U64 pack2(float a, float b) {
    U64 d;
    asm("mov.b64 %0, {%1, %2};" : "=l"(d)
        : "r"(__float_as_uint(a)), "r"(__float_as_uint(b)));
    return d;
}
__device__ __forceinline__ float lo2(U64 v) { return __uint_as_float((unsigned)(v & 0xffffffffu)); }
__device__ __forceinline__ float hi2(U64 v) { return __uint_as_float((unsigned)(v >> 32)); }

__device__ __forceinline__ void cpa16(void* dst, const void* src) {
    unsigned d = (unsigned)__cvta_generic_to_shared(dst);
    asm volatile("cp.async.cg.shared.global [%0], [%1], 16;\n" :: "r"(d), "l"(src));
}
#define CP_COMMIT() asm volatile("cp.async.commit_group;\n" ::: "memory")
#define CP_WAIT0()  asm volatile("cp.async.wait_group 0;\n" ::: "memory")

// ---------------- zero kernels (atomic accumulators) ----------------
__global__ void zero_y_kernel() {
    int i = (blockIdx.x * 256 + threadIdx.x) * 4;   // 1024 CTAs -> 1,048,576 floats
    *(float4*)&(((float*)g_y)[i]) = make_float4(0.f, 0.f, 0.f, 0.f);
}
__global__ void zero_d_kernel() {
    int i = blockIdx.x * 256 + threadIdx.x;          // 8 CTAs -> 2048 floats
    ((float*)g_denom)[i] = 0.f;
}

// ---------------- qk fold (64 CTAs, smem-staged coalesced) ----------------
__global__ __launch_bounds__(256) void qk_kernel(const float* __restrict__ q,
                                                 const float* __restrict__ kw) {
    __shared__ float tile[64 * 65];
    __shared__ float qs[64];
    __shared__ float part[4][64];
    const int h = blockIdx.x >> 3, jb = blockIdx.x & 7;
    const int t = threadIdx.x;
    if (t < 64) qs[t] = q[h * 64 + t];
    for (int k = t; k < 1024; k += 256) {
        int r = k >> 4, cc = k & 15;
        float4 v = *(const float4*)&kw[(size_t)(h * 64 + r) * HDIM + jb * 64 + cc * 4];
        float* dst = &tile[r * 65 + cc * 4];
        dst[0] = v.x; dst[1] = v.y; dst[2] = v.z; dst[3] = v.w;
    }
    __syncthreads();
    const int c = t & 63, ds = t >> 6;
    float s = 0.f;
#pragma unroll
    for (int d = 0; d < 16; d++) s += qs[ds * 16 + d] * tile[(ds * 16 + d) * 65 + c];
    part[ds][c] = s;
    __syncthreads();
    if (t < 64)
        g_qk[h * HDIM + jb * 64 + t] =
            (part[0][t] + part[1][t] + part[2][t] + part[3][t]) * 0.125f;
}

// ---------------- main: warp-autonomous, register-resident, 2-deep pipelined ----------------
// Warp w: heads {2(w&3), 2(w&3)+1}, node-lane nl = w>>2 -> 64 contiguous nodes.
// Lane owns 16 dims as 4 float4s: floats p*128 + lane*4 + {0..3}, p = 0..3.
// Per node: 4 LDG.128 (prefetched one node ahead) -> Phase A vs stationary q regs
// (4 independent fma2 chains) -> 5-shfl butterfly -> exp -> Phase B into Y regs.
// Graph boundary -> spread atomicAdd flush. No smem, no __syncthreads.
__global__ __launch_bounds__(256, 2)
void main_kernel(const float* __restrict__ x, const int* __restrict__ batch, int N) {
    const int t = threadIdx.x;
    const int lane = t & 31;
    const int w = t >> 5;
    const int h0 = (w & 3) * 2;
    const int nl = w >> 2;

    // stationary folded-query regs (2 heads x 4 float4s)
    U64 q0[8], q1[8];
#pragma unroll
    for (int p = 0; p < 4; p++) {
        int d = p * 128 + lane * 4;
        ulonglong2 a = *(const ulonglong2*)&g_qk[h0 * HDIM + d];
        ulonglong2 b = *(const ulonglong2*)&g_qk[(h0 + 1) * HDIM + d];
        q0[2 * p] = a.x; q0[2 * p + 1] = a.y;
        q1[2 * p] = b.x; q1[2 * p + 1] = b.y;
    }

    U64 Y0[8], Y1[8];
#pragma unroll
    for (int p = 0; p < 8; p++) { Y0[p] = 0ull; Y1[p] = 0ull; }
    U64 dp = 0ull;
    int cur_g = -1;

    const int nbeg = blockIdx.x * CH + nl * (CH / 2);
    const int nlim = min(nbeg + CH / 2, N);

#define FLUSH() do {                                                          \
        _Pragma("unroll")                                                     \
        for (int p = 0; p < 4; p++) {                                         \
            int d = p * 128 + lane * 4;                                       \
            atomicAdd(&g_y[cur_g][h0][d],         lo2(Y0[2 * p]));            \
            atomicAdd(&g_y[cur_g][h0][d + 1],     hi2(Y0[2 * p]));            \
            atomicAdd(&g_y[cur_g][h0][d + 2],     lo2(Y0[2 * p + 1]));        \
            atomicAdd(&g_y[cur_g][h0][d + 3],     hi2(Y0[2 * p + 1]));        \
            atomicAdd(&g_y[cur_g][h0 + 1][d],     lo2(Y1[2 * p]));            \
            atomicAdd(&g_y[cur_g][h0 + 1][d + 1], hi2(Y1[2 * p]));            \
            atomicAdd(&g_y[cur_g][h0 + 1][d + 2], lo2(Y1[2 * p + 1]));        \
            atomicAdd(&g_y[cur_g][h0 + 1][d + 3], hi2(Y1[2 * p + 1]));        \
            Y0[2 * p] = 0ull; Y0[2 * p + 1] = 0ull;                           \
            Y1[2 * p] = 0ull; Y1[2 * p + 1] = 0ull;                           \
        }                                                                     \
        if (lane == 0) {                                                      \
            atomicAdd(&g_denom[cur_g][h0],     lo2(dp));                      \
            atomicAdd(&g_denom[cur_g][h0 + 1], hi2(dp));                      \
        }                                                                     \
        dp = 0ull;                                                            \
    } while (0)

    // 4 x LDG.128 per node, coalesced 512B per load across the warp
#define LOADX(buf, n) do {                                                    \
        const float* xr = x + (size_t)(n) * HDIM + lane * 4;                  \
        _Pragma("unroll")                                                     \
        for (int p = 0; p < 4; p++) {                                         \
            ulonglong2 v = *(const ulonglong2*)&xr[p * 128];                  \
            buf[2 * p] = v.x; buf[2 * p + 1] = v.y;                           \
        }                                                                     \
    } while (0)

#define PROC(buf, n) do {                                                     \
        int gi = batch[n];                                                    \
        if (gi != cur_g) {                                                    \
            if (cur_g >= 0) FLUSH();                                          \
            cur_g = gi;                                                       \
        }                                                                     \
        U64 a0 = 0ull, a1 = 0ull, b0 = 0ull, b1 = 0ull;                       \
        _Pragma("unroll")                                                     \
        for (int p = 0; p < 4; p++) {                                         \
            a0 = fma2(buf[2 * p],     q0[2 * p],     a0);                     \
            a1 = fma2(buf[2 * p + 1], q0[2 * p + 1], a1);                     \
            b0 = fma2(buf[2 * p],     q1[2 * p],     b0);                     \
            b1 = fma2(buf[2 * p + 1], q1[2 * p + 1], b1);                     \
        }                                                                     \
        a0 = add2(a0, a1); b0 = add2(b0, b1);                                 \
        float s0 = lo2(a0) + hi2(a0);                                         \
        float s1 = lo2(b0) + hi2(b0);                                         \
        _Pragma("unroll")                                                     \
        for (int o = 16; o; o >>= 1) {                                        \
            s0 += __shfl_xor_sync(~0u, s0, o);                                \
            s1 += __shfl_xor_sync(~0u, s1, o);                                \
        }                                                                     \
        float w0 = __expf(s0), w1 = __expf(s1);                               \
        dp = add2(dp, pack2(w0, w1));                                         \
        U64 wd0 = dup2(w0), wd1 = dup2(w1);                                   \
        _Pragma("unroll")                                                     \
        for (int p = 0; p < 8; p++) {                                         \
            Y0[p] = fma2(wd0, buf[p], Y0[p]);                                 \
            Y1[p] = fma2(wd1, buf[p], Y1[p]);                                 \
        }                                                                     \
    } while (0)

    U64 XA[8], XB[8];
    if (nbeg < nlim) LOADX(XA, nbeg);

    int n = nbeg;
    while (n < nlim) {
        if (n + 1 < nlim) LOADX(XB, n + 1);   // prefetch overlaps PROC(XA)
        PROC(XA, n);
        n++;
        if (n >= nlim) break;
        if (n + 1 < nlim) LOADX(XA, n + 1);   // prefetch overlaps PROC(XB)
        PROC(XB, n);
        n++;
    }

    if (cur_g >= 0) FLUSH();
#undef PROC
#undef LOADX
#undef FLUSH
}

// ---------------- v-projection: grid (64 graph-blocks of 4, 8 heads) ----------------
__global__ __launch_bounds__(256) void vproj_kernel(const float* __restrict__ vw,
                                                    const float* __restrict__ vb) {
    __shared__ float Yn[4][HDIM];
    __shared__ float wt[2][64][68];
    __shared__ float invs[4], nzf[4];
    const int gb = blockIdx.x, h = blockIdx.y, t = threadIdx.x;

    if (t < 4) {
        float d = g_denom[gb * 4 + t][h];
        invs[t] = d > 0.f ? 1.f / d : 0.f;
        nzf[t]  = d > 0.f ? 1.f : 0.f;
    }
    __syncthreads();

    for (int k = t * 4; k < 4 * HDIM; k += 1024) {
        int r = k >> 9, cidx = k & 511;
        float4 v = *(const float4*)&g_y[gb * 4 + r][h][cidx];
        float s = invs[r];
        v.x *= s; v.y *= s; v.z *= s; v.w *= s;
        *(float4*)&Yn[r][cidx] = v;
    }

#define LOAD_W(KC, BUF) do {                                                  \
        _Pragma("unroll")                                                     \
        for (int k = 0; k < 4; k++) {                                         \
            int idx = t + k * 256;                                            \
            int r = idx >> 4, cc = idx & 15;                                  \
            cpa16(&wt[BUF][r][cc * 4],                                        \
                  &vw[(size_t)(h * 64 + r) * HDIM + (KC) + cc * 4]);          \
        }                                                                     \
    } while (0)

    LOAD_W(0, 0);
    CP_COMMIT();

    const int c = t & 63, gq = t >> 6;
    U64 a0 = 0ull, a1 = 0ull;

    for (int ch = 0; ch < 8; ch++) {
        CP_WAIT0();
        __syncthreads();
        if (ch + 1 < 8) LOAD_W((ch + 1) * 64, (ch + 1) & 1);
        CP_COMMIT();

        const float* wr = &wt[ch & 1][c][0];
#pragma unroll
        for (int j = 0; j < 64; j += 4) {
            ulonglong2 w2 = *(const ulonglong2*)&wr[j];
            ulonglong2 ya = *(const ulonglong2*)&Yn[gq][ch * 64 + j];
            a0 = fma2(w2.x, ya.x, a0);
            a1 = fma2(w2.y, ya.y, a1);
        }
        __syncthreads();
    }
#undef LOAD_W

    float b = vb[h * 64 + c];
    float r = lo2(a0) + hi2(a0) + lo2(a1) + hi2(a1);
    g_att[gb * 4 + gq][h * 64 + c] = r + nzf[gq] * b;
}

// ---------------- output projection: grid (64 graph-blocks of 4, 8 col-blocks) ----------------
__global__ __launch_bounds__(256) void oproj_kernel(const float* __restrict__ ow,
                                                    const float* __restrict__ ob,
                                                    float* __restrict__ out) {
    __shared__ float As[4][HDIM];
    __shared__ float wt[2][64][68];
    const int gb = blockIdx.x, ib = blockIdx.y, t = threadIdx.x;

    for (int k = t * 4; k < 4 * HDIM; k += 1024) {
        int r = k >> 9, cidx = k & 511;
        *(float4*)&As[r][cidx] = *(const float4*)&g_att[gb * 4 + r][cidx];
    }

#define LOAD_W(KC, BUF) do {                                                  \
        _Pragma("unroll")                                                     \
        for (int k = 0; k < 4; k++) {                                         \
            int idx = t + k * 256;                                            \
            int r = idx >> 4, cc = idx & 15;                                  \
            cpa16(&wt[BUF][r][cc * 4],                                        \
                  &ow[(size_t)(ib * 64 + r) * HDIM + (KC) + cc * 4]);         \
        }                                                                     \
    } while (0)

    LOAD_W(0, 0);
    CP_COMMIT();

    const int c = t & 63, gq = t >> 6;
    U64 a0 = 0ull, a1 = 0ull;

    for (int ch = 0; ch < 8; ch++) {
        CP_WAIT0();
        __syncthreads();
        if (ch + 1 < 8) LOAD_W((ch + 1) * 64, (ch + 1) & 1);
        CP_COMMIT();

        const float* wr = &wt[ch & 1][c][0];
#pragma unroll
        for (int j = 0; j < 64; j += 4) {
            ulonglong2 w2 = *(const ulonglong2*)&wr[j];
            ulonglong2 ya = *(const ulonglong2*)&As[gq][ch * 64 + j];
            a0 = fma2(w2.x, ya.x, a0);
            a1 = fma2(w2.y, ya.y, a1);
        }
        __syncthreads();
    }
#undef LOAD_W

    float b = ob[ib * 64 + c];
    float r = lo2(a0) + hi2(a0) + lo2(a1) + hi2(a1);
    out[(size_t)(gb * 4 + gq) * HDIM + ib * 64 + c] = r + b;
}

// ---------------- layer norm (in place on d_out) ----------------
__global__ void ln_kernel(const float* __restrict__ gam, const float* __restrict__ bet,
                          float* __restrict__ out) {
    __shared__ float red1[8], red2[8], stats[2];
    int r = blockIdx.x, t = threadIdx.x;
    float v0 = out[(size_t)r * HDIM + t];
    float v1 = out[(size_t)r * HDIM + t + 256];
    float s1 = v0 + v1, s2 = v0 * v0 + v1 * v1;
#pragma unroll
    for (int o = 16; o; o >>= 1) {
        s1 += __shfl_xor_sync(~0u, s1, o);
        s2 += __shfl_xor_sync(~0u, s2, o);
    }
    if ((t & 31) == 0) { red1[t >> 5] = s1; red2[t >> 5] = s2; }
    __syncthreads();
    if (t == 0) {
        float a = 0.f, b = 0.f;
        for (int k = 0; k < 8; k++) { a += red1[k]; b += red2[k]; }
        float mu = a * (1.f / 512.f);
        stats[0] = mu;
        stats[1] = rsqrtf(b * (1.f / 512.f) - mu * mu + 1e-5f);
    }
    __syncthreads();
    float mu = stats[0], rs = stats[1];
    out[(size_t)r * HDIM + t]       = (v0 - mu) * rs * gam[t] + bet[t];
    out[(size_t)r * HDIM + t + 256] = (v1 - mu) * rs * gam[t + 256] + bet[t + 256];
}

// ---------------- launch ----------------
extern "C" void kernel_launch(void* const* d_in, const int* in_sizes, int n_in,
                              void* d_out, int out_size) {
    const float* x     = (const float*)d_in[0];
    const int*   batch = (const int*)d_in[1];
    const float* q     = (const float*)d_in[2];
    const float* kw    = (const float*)d_in[3];
    // d_in[4] = k_b: cancels in segment softmax (per-head constant shift) — unused
    const float* vw    = (const float*)d_in[5];
    const float* vb    = (const float*)d_in[6];
    const float* ow    = (const float*)d_in[7];
    const float* ob    = (const float*)d_in[8];
    const float* lng   = (const float*)d_in[9];
    const float* lnb   = (const float*)d_in[10];
    float* out = (float*)d_out;

    int N = in_sizes[0] / HDIM;

    zero_y_kernel<<<1024, 256>>>();                 // launch 1
    zero_d_kernel<<<8, 256>>>();                    // launch 2
    qk_kernel<<<64, 256>>>(q, kw);                  // launch 3

    int NT = (N + CH - 1) / CH;
    main_kernel<<<NT, 256>>>(x, batch, N);          // launch 4 (profiled slot)

    vproj_kernel<<<dim3(64, NUM_HEADS), 256>>>(vw, vb);
    oproj_kernel<<<dim3(64, NUM_HEADS), 256>>>(ow, ob, out);
    ln_kernel<<<NGRAPH, 256>>>(lng, lnb, out);
}